// round 1
// baseline (speedup 1.0000x reference)
#include <cuda_runtime.h>
#include <cstdint>

// Problem constants (fixed by the reference setup)
#define MTOK 8192      // B*T = 4*2048
#define TLEN 2048
#define HDIM 4096
#define DBOT 1024
#define PP   8
#define DD   64
#define KKF  64
#define COMBDIM 128    // D + K

// ---------------- scratch (device globals; no allocation allowed) ----------
__device__ float g_hbot [ (size_t)MTOK * DBOT ];            // 33.5 MB
__device__ float g_base [ (size_t)MTOK * PP * DD ];         // 16.8 MB
__device__ float g_fiber[ (size_t)MTOK * PP * KKF ];        // 16.8 MB
__device__ float g_wlog [ (size_t)MTOK * PP ];              // 0.26 MB
__device__ float g_comb [ (size_t)MTOK * COMBDIM ];         // 4.2 MB

// ---------------------------------------------------------------------------
// Classic 128x128x8 register-blocked SGEMM.
// C[M,N] = A[M,K] @ B[K,N] + bias[N]  (+ residual[M,N] if ADD_RES)
// Requires: M%128==0, N%128==0, K%8==0. 256 threads, each computes 8x8.
// ---------------------------------------------------------------------------
template<bool ADD_RES>
__global__ __launch_bounds__(256)
void sgemm_kernel(const float* __restrict__ A,
                  const float* __restrict__ B,
                  const float* __restrict__ bias,
                  const float* __restrict__ res,
                  float* __restrict__ C,
                  int M, int N, int K)
{
    __shared__ float As[8][128];   // transposed A tile: As[k][m]
    __shared__ float Bs[8][128];   // Bs[k][n]

    const int bx = blockIdx.x;     // N tile index
    const int by = blockIdx.y;     // M tile index
    const int tid = threadIdx.x;

    // A tile load mapping: 128 rows x 8 cols, one float4 per thread
    const int aRow  = tid >> 1;          // 0..127
    const int aCol4 = (tid & 1) * 4;     // 0 or 4
    // B tile load mapping: 8 rows x 128 cols, one float4 per thread
    const int bRow  = tid >> 5;          // 0..7
    const int bCol4 = (tid & 31) * 4;    // 0..124

    const int tx = tid & 15;             // 0..15 -> N micro
    const int ty = tid >> 4;             // 0..15 -> M micro

    float acc[8][8];
#pragma unroll
    for (int i = 0; i < 8; i++)
#pragma unroll
        for (int j = 0; j < 8; j++) acc[i][j] = 0.0f;

    const float* Ablk = A + (size_t)(by * 128) * K;
    const float* Bblk = B + (size_t)(bx * 128);

    for (int k0 = 0; k0 < K; k0 += 8) {
        // load A tile (transposed into smem)
        float4 av = *reinterpret_cast<const float4*>(Ablk + (size_t)aRow * K + k0 + aCol4);
        As[aCol4 + 0][aRow] = av.x;
        As[aCol4 + 1][aRow] = av.y;
        As[aCol4 + 2][aRow] = av.z;
        As[aCol4 + 3][aRow] = av.w;
        // load B tile
        float4 bv = *reinterpret_cast<const float4*>(Bblk + (size_t)(k0 + bRow) * N + bCol4);
        *reinterpret_cast<float4*>(&Bs[bRow][bCol4]) = bv;
        __syncthreads();

#pragma unroll
        for (int k = 0; k < 8; k++) {
            float a[8], b[8];
#pragma unroll
            for (int i = 0; i < 8; i++) a[i] = As[k][ty * 8 + i];
#pragma unroll
            for (int j = 0; j < 8; j++) b[j] = Bs[k][tx * 8 + j];
#pragma unroll
            for (int i = 0; i < 8; i++)
#pragma unroll
                for (int j = 0; j < 8; j++)
                    acc[i][j] = fmaf(a[i], b[j], acc[i][j]);
        }
        __syncthreads();
    }

    // epilogue
#pragma unroll
    for (int i = 0; i < 8; i++) {
        const int row = by * 128 + ty * 8 + i;
#pragma unroll
        for (int j = 0; j < 8; j += 4) {
            const int col = bx * 128 + tx * 8 + j;
            float4 bb = *reinterpret_cast<const float4*>(bias + col);
            float4 v;
            v.x = acc[i][j + 0] + bb.x;
            v.y = acc[i][j + 1] + bb.y;
            v.z = acc[i][j + 2] + bb.z;
            v.w = acc[i][j + 3] + bb.w;
            if (ADD_RES) {
                float4 r = *reinterpret_cast<const float4*>(res + (size_t)row * N + col);
                v.x += r.x; v.y += r.y; v.z += r.z; v.w += r.w;
            }
            *reinterpret_cast<float4*>(C + (size_t)row * N + col) = v;
        }
    }
}

// ---------------------------------------------------------------------------
// w_logits: per token, 8 outputs, dot over DBOT=1024.
// One block (256 threads = 8 warps) per token; warp p computes logit p.
// ---------------------------------------------------------------------------
__global__ __launch_bounds__(256)
void wlog_kernel(const float* __restrict__ Ww, const float* __restrict__ bw)
{
    const int t    = blockIdx.x;
    const int warp = threadIdx.x >> 5;
    const int lane = threadIdx.x & 31;
    const float* h = g_hbot + (size_t)t * DBOT;

    float s = 0.0f;
#pragma unroll 4
    for (int k = lane; k < DBOT; k += 32)
        s += h[k] * Ww[k * PP + warp];
#pragma unroll
    for (int o = 16; o > 0; o >>= 1)
        s += __shfl_xor_sync(0xffffffffu, s, o);
    if (lane == 0)
        g_wlog[(size_t)t * PP + warp] = s + bw[warp];
}

// ---------------------------------------------------------------------------
// Pointwise: clip base, temporal transport, softmax over P, aggregate.
// One block (128 threads) per token; thread d handles combined[d].
// ---------------------------------------------------------------------------
__global__ __launch_bounds__(128)
void pointwise_kernel()
{
    const int t   = blockIdx.x;
    const int bt  = t & (TLEN - 1);   // t within batch (TLEN power of 2)
    const int tid = threadIdx.x;

    __shared__ float w[PP];
    if (tid < PP) w[tid] = g_wlog[(size_t)t * PP + tid];
    __syncthreads();
    if (tid == 0) {
        float mx = w[0];
#pragma unroll
        for (int p = 1; p < PP; p++) mx = fmaxf(mx, w[p]);
        float sum = 0.0f;
#pragma unroll
        for (int p = 0; p < PP; p++) { w[p] = __expf(w[p] - mx); sum += w[p]; }
        const float inv = 1.0f / sum;
#pragma unroll
        for (int p = 0; p < PP; p++) w[p] *= inv;
    }
    __syncthreads();

    float out = 0.0f;
    if (tid < DD) {
        const int d = tid;
        const float* bc = g_base + (size_t)t * PP * DD;
        const bool first = (bt == 0);
        if (first) {
#pragma unroll
            for (int p = 0; p < PP; p++) {
                float c = fminf(fmaxf(bc[p * DD + d], -10.0f), 10.0f);
                out += w[p] * c;
            }
        } else {
            const float* bp = g_base + (size_t)(t - 1) * PP * DD;
#pragma unroll
            for (int p = 0; p < PP; p++) {
                float c  = fminf(fmaxf(bc[p * DD + d], -10.0f), 10.0f);
                float pv = fminf(fmaxf(bp[p * DD + d], -10.0f), 10.0f);
                out += w[p] * (0.9f * c + 0.1f * pv);
            }
        }
    } else {
        const int kd = tid - DD;
        const float* f = g_fiber + (size_t)t * PP * KKF;
#pragma unroll
        for (int p = 0; p < PP; p++)
            out += w[p] * f[p * KKF + kd];
    }
    g_comb[(size_t)t * COMBDIM + tid] = out;
}

// ---------------------------------------------------------------------------
// Launch. Input order (metadata):
// 0:x 1:Wi 2:bi 3:Wb 4:bb 5:Wf 6:bf 7:Wl 8:bl 9:Ww 10:bw
// 11:Wm 12:bm 13:Ws 14:bs 15:Wu 16:bu 17:Wo 18:bo
// (Wl/Wm/Ws/Wu projections are dead code in the reference — skipped.)
// ---------------------------------------------------------------------------
extern "C" void kernel_launch(void* const* d_in, const int* in_sizes, int n_in,
                              void* d_out, int out_size)
{
    const float* x  = (const float*)d_in[0];
    const float* Wi = (const float*)d_in[1];
    const float* bi = (const float*)d_in[2];
    const float* Wb = (const float*)d_in[3];
    const float* bb = (const float*)d_in[4];
    const float* Wf = (const float*)d_in[5];
    const float* bf = (const float*)d_in[6];
    const float* Ww = (const float*)d_in[9];
    const float* bw = (const float*)d_in[10];
    const float* Wo = (const float*)d_in[17];
    const float* bo = (const float*)d_in[18];
    float* out = (float*)d_out;

    float *hbot, *base, *fiber, *comb;
    cudaGetSymbolAddress((void**)&hbot,  g_hbot);
    cudaGetSymbolAddress((void**)&base,  g_base);
    cudaGetSymbolAddress((void**)&fiber, g_fiber);
    cudaGetSymbolAddress((void**)&comb,  g_comb);

    // 1) h_bot = x @ Wi + bi          [8192,1024], K=4096
    sgemm_kernel<false><<<dim3(DBOT / 128, MTOK / 128), 256>>>(
        x, Wi, bi, nullptr, hbot, MTOK, DBOT, HDIM);

    // 2) base = h_bot @ Wb + bb       [8192,512], K=1024
    sgemm_kernel<false><<<dim3((PP * DD) / 128, MTOK / 128), 256>>>(
        hbot, Wb, bb, nullptr, base, MTOK, PP * DD, DBOT);

    //    fiber = h_bot @ Wf + bf      [8192,512], K=1024
    sgemm_kernel<false><<<dim3((PP * KKF) / 128, MTOK / 128), 256>>>(
        hbot, Wf, bf, nullptr, fiber, MTOK, PP * KKF, DBOT);

    //    w_logits = h_bot @ Ww + bw   [8192,8]
    wlog_kernel<<<MTOK, 256>>>(Ww, bw);

    // 3) softmax / transport / aggregate -> combined [8192,128]
    pointwise_kernel<<<MTOK, 128>>>();

    // 4) out = x + combined @ Wo + bo  [8192,4096], K=128
    sgemm_kernel<true><<<dim3(HDIM / 128, MTOK / 128), 256>>>(
        comb, Wo, bo, x, out, MTOK, HDIM, COMBDIM);
}

// round 2
// speedup vs baseline: 1.0875x; 1.0875x over previous
#include <cuda_runtime.h>
#include <cstdint>

// Problem constants (fixed by the reference setup)
#define MTOK 8192      // B*T = 4*2048
#define TLEN 2048
#define HDIM 4096
#define DBOT 1024
#define PP   8
#define DD   64
#define KKF  64
#define COMBDIM 128    // D + K

// ---------------- scratch (device globals; no allocation allowed) ----------
__device__ float g_hbot [ (size_t)MTOK * DBOT ];
__device__ float g_base [ (size_t)MTOK * PP * DD ];
__device__ float g_fiber[ (size_t)MTOK * PP * KKF ];
__device__ float g_wlog [ (size_t)MTOK * PP ];
__device__ float g_comb [ (size_t)MTOK * COMBDIM ];

// ---------------- cp.async helpers ----------------------------------------
__device__ __forceinline__ void cp16(uint32_t s, const void* g) {
    asm volatile("cp.async.cg.shared.global [%0], [%1], 16;" :: "r"(s), "l"(g));
}
__device__ __forceinline__ void cp_commit() { asm volatile("cp.async.commit_group;"); }
__device__ __forceinline__ void cp_wait0()  { asm volatile("cp.async.wait_group 0;"); }

// ---------------------------------------------------------------------------
// 128x128x16 double-buffered SGEMM core (cp.async pipeline, 256 thr, 8x8 micro)
// C[M,N] = A[M,K] @ B[K,N] + bias[N]  (+ res[M,N] if ADD_RES)
// M,N multiples of 128; K multiple of 16.
// ---------------------------------------------------------------------------
template<bool ADD_RES>
__device__ __forceinline__ void sgemm_core(const float* __restrict__ A,
                                           const float* __restrict__ B,
                                           const float* __restrict__ bias,
                                           const float* __restrict__ res,
                                           float* __restrict__ C,
                                           int M, int N, int K,
                                           int bx, int by)
{
    __shared__ __align__(16) float sA[2][128 * 16];   // [m][k], 8 KB each
    __shared__ __align__(16) float sB[2][16 * 128];   // [k][n], 8 KB each

    const int tid = threadIdx.x;
    const int tx = tid & 15;     // N micro
    const int ty = tid >> 4;     // M micro

    const float* Ablk = A + (size_t)(by * 128) * K;
    const float* Bblk = B + (size_t)(bx * 128);

    uint32_t sA0 = (uint32_t)__cvta_generic_to_shared(&sA[0][0]);
    uint32_t sB0 = (uint32_t)__cvta_generic_to_shared(&sB[0][0]);

    // Per-thread load mapping (2 x 16B for A, 2 x 16B for B per stage)
    const int ar = tid >> 2;            // 0..63 (and +64)
    const int ac = (tid & 3) * 4;       // 0,4,8,12
    const int br = tid >> 5;            // 0..7 (and +8)
    const int bc = (tid & 31) * 4;      // 0..124

    float acc[8][8];
#pragma unroll
    for (int i = 0; i < 8; i++)
#pragma unroll
        for (int j = 0; j < 8; j++) acc[i][j] = 0.0f;

    const int steps = K >> 4;

    // prologue: stage 0
    {
        uint32_t ab = sA0, bb2 = sB0;
        cp16(ab + (ar * 16 + ac) * 4,        Ablk + (size_t)ar * K + ac);
        cp16(ab + ((ar + 64) * 16 + ac) * 4, Ablk + (size_t)(ar + 64) * K + ac);
        cp16(bb2 + (br * 128 + bc) * 4,       Bblk + (size_t)br * N + bc);
        cp16(bb2 + ((br + 8) * 128 + bc) * 4, Bblk + (size_t)(br + 8) * N + bc);
        cp_commit();
    }

    for (int s = 0; s < steps; s++) {
        cp_wait0();
        __syncthreads();   // stage s visible; all warps done computing stage s-1

        if (s + 1 < steps) {
            const int k0 = (s + 1) << 4;
            const int nb = (s + 1) & 1;
            uint32_t ab = sA0 + nb * (128 * 16 * 4);
            uint32_t bb2 = sB0 + nb * (16 * 128 * 4);
            cp16(ab + (ar * 16 + ac) * 4,        Ablk + (size_t)ar * K + k0 + ac);
            cp16(ab + ((ar + 64) * 16 + ac) * 4, Ablk + (size_t)(ar + 64) * K + k0 + ac);
            cp16(bb2 + (br * 128 + bc) * 4,       Bblk + (size_t)(k0 + br) * N + bc);
            cp16(bb2 + ((br + 8) * 128 + bc) * 4, Bblk + (size_t)(k0 + br + 8) * N + bc);
            cp_commit();
        }

        const float* As = sA[s & 1];
        const float* Bs = sB[s & 1];
#pragma unroll
        for (int k = 0; k < 16; k++) {
            float a[8], b[8];
#pragma unroll
            for (int i = 0; i < 8; i++) a[i] = As[(ty * 8 + i) * 16 + k];
            float4 b0 = *reinterpret_cast<const float4*>(&Bs[k * 128 + tx * 8]);
            float4 b1 = *reinterpret_cast<const float4*>(&Bs[k * 128 + tx * 8 + 4]);
            b[0] = b0.x; b[1] = b0.y; b[2] = b0.z; b[3] = b0.w;
            b[4] = b1.x; b[5] = b1.y; b[6] = b1.z; b[7] = b1.w;
#pragma unroll
            for (int i = 0; i < 8; i++)
#pragma unroll
                for (int j = 0; j < 8; j++)
                    acc[i][j] = fmaf(a[i], b[j], acc[i][j]);
        }
        // no trailing sync: next iteration's wait+sync guards buffer reuse
    }

    // epilogue
#pragma unroll
    for (int i = 0; i < 8; i++) {
        const int row = by * 128 + ty * 8 + i;
#pragma unroll
        for (int j = 0; j < 8; j += 4) {
            const int col = bx * 128 + tx * 8 + j;
            float4 bb = *reinterpret_cast<const float4*>(bias + col);
            float4 v;
            v.x = acc[i][j + 0] + bb.x;
            v.y = acc[i][j + 1] + bb.y;
            v.z = acc[i][j + 2] + bb.z;
            v.w = acc[i][j + 3] + bb.w;
            if (ADD_RES) {
                float4 r = *reinterpret_cast<const float4*>(res + (size_t)row * N + col);
                v.x += r.x; v.y += r.y; v.z += r.z; v.w += r.w;
            }
            *reinterpret_cast<float4*>(C + (size_t)row * N + col) = v;
        }
    }
}

template<bool ADD_RES>
__global__ __launch_bounds__(256)
void sgemm_kernel(const float* __restrict__ A, const float* __restrict__ B,
                  const float* __restrict__ bias, const float* __restrict__ res,
                  float* __restrict__ C, int M, int N, int K)
{
    sgemm_core<ADD_RES>(A, B, bias, res, C, M, N, K, blockIdx.x, blockIdx.y);
}

// Fused base+fiber projections: grid.x = 8; bx<4 -> Wb->g_base, else Wf->g_fiber
__global__ __launch_bounds__(256)
void gemm23_kernel(const float* __restrict__ hbot,
                   const float* __restrict__ Wb, const float* __restrict__ bb,
                   const float* __restrict__ Wf, const float* __restrict__ bf)
{
    const bool lo = (blockIdx.x < 4);
    const float* Bp   = lo ? Wb : Wf;
    const float* bias = lo ? bb : bf;
    float*       Cp   = lo ? g_base : g_fiber;
    sgemm_core<false>(hbot, Bp, bias, nullptr, Cp,
                      MTOK, PP * DD, DBOT, blockIdx.x & 3, blockIdx.y);
}

// ---------------------------------------------------------------------------
// w_logits: warp per token. Lane l handles k = l, l+32, ...; Ww row k is a
// contiguous 32B chunk -> coalesced. acc[8] per lane, butterfly-reduce.
// ---------------------------------------------------------------------------
__global__ __launch_bounds__(256)
void wlog_kernel(const float* __restrict__ Ww, const float* __restrict__ bw)
{
    const int warp = threadIdx.x >> 5;
    const int lane = threadIdx.x & 31;
    const int t = blockIdx.x * 8 + warp;
    const float* h = g_hbot + (size_t)t * DBOT;

    float acc[PP];
#pragma unroll
    for (int p = 0; p < PP; p++) acc[p] = 0.0f;

#pragma unroll 4
    for (int k = lane; k < DBOT; k += 32) {
        const float hv = h[k];
        float4 w0 = *reinterpret_cast<const float4*>(Ww + (size_t)k * PP);
        float4 w1 = *reinterpret_cast<const float4*>(Ww + (size_t)k * PP + 4);
        acc[0] = fmaf(hv, w0.x, acc[0]);
        acc[1] = fmaf(hv, w0.y, acc[1]);
        acc[2] = fmaf(hv, w0.z, acc[2]);
        acc[3] = fmaf(hv, w0.w, acc[3]);
        acc[4] = fmaf(hv, w1.x, acc[4]);
        acc[5] = fmaf(hv, w1.y, acc[5]);
        acc[6] = fmaf(hv, w1.z, acc[6]);
        acc[7] = fmaf(hv, w1.w, acc[7]);
    }
#pragma unroll
    for (int p = 0; p < PP; p++) {
#pragma unroll
        for (int o = 16; o > 0; o >>= 1)
            acc[p] += __shfl_xor_sync(0xffffffffu, acc[p], o);
    }
    if (lane < PP)
        g_wlog[(size_t)t * PP + lane] = acc[lane] + bw[lane];
}

// ---------------------------------------------------------------------------
// Pointwise: clip base, temporal transport, softmax over P, aggregate.
// ---------------------------------------------------------------------------
__global__ __launch_bounds__(128)
void pointwise_kernel()
{
    const int t   = blockIdx.x;
    const int bt  = t & (TLEN - 1);
    const int tid = threadIdx.x;

    __shared__ float w[PP];
    if (tid < PP) w[tid] = g_wlog[(size_t)t * PP + tid];
    __syncthreads();
    if (tid == 0) {
        float mx = w[0];
#pragma unroll
        for (int p = 1; p < PP; p++) mx = fmaxf(mx, w[p]);
        float sum = 0.0f;
#pragma unroll
        for (int p = 0; p < PP; p++) { w[p] = __expf(w[p] - mx); sum += w[p]; }
        const float inv = 1.0f / sum;
#pragma unroll
        for (int p = 0; p < PP; p++) w[p] *= inv;
    }
    __syncthreads();

    float out = 0.0f;
    if (tid < DD) {
        const int d = tid;
        const float* bc = g_base + (size_t)t * PP * DD;
        if (bt == 0) {
#pragma unroll
            for (int p = 0; p < PP; p++) {
                float c = fminf(fmaxf(bc[p * DD + d], -10.0f), 10.0f);
                out += w[p] * c;
            }
        } else {
            const float* bp = g_base + (size_t)(t - 1) * PP * DD;
#pragma unroll
            for (int p = 0; p < PP; p++) {
                float c  = fminf(fmaxf(bc[p * DD + d], -10.0f), 10.0f);
                float pv = fminf(fmaxf(bp[p * DD + d], -10.0f), 10.0f);
                out += w[p] * (0.9f * c + 0.1f * pv);
            }
        }
    } else {
        const int kd = tid - DD;
        const float* f = g_fiber + (size_t)t * PP * KKF;
#pragma unroll
        for (int p = 0; p < PP; p++)
            out += w[p] * f[p * KKF + kd];
    }
    g_comb[(size_t)t * COMBDIM + tid] = out;
}

// ---------------------------------------------------------------------------
// Inputs: 0:x 1:Wi 2:bi 3:Wb 4:bb 5:Wf 6:bf 7:Wl 8:bl 9:Ww 10:bw
//         11:Wm 12:bm 13:Ws 14:bs 15:Wu 16:bu 17:Wo 18:bo
// (Wl/Wm/Ws/Wu projections are dead code in the reference — skipped.)
// ---------------------------------------------------------------------------
extern "C" void kernel_launch(void* const* d_in, const int* in_sizes, int n_in,
                              void* d_out, int out_size)
{
    const float* x  = (const float*)d_in[0];
    const float* Wi = (const float*)d_in[1];
    const float* bi = (const float*)d_in[2];
    const float* Wb = (const float*)d_in[3];
    const float* bb = (const float*)d_in[4];
    const float* Wf = (const float*)d_in[5];
    const float* bf = (const float*)d_in[6];
    const float* Ww = (const float*)d_in[9];
    const float* bw = (const float*)d_in[10];
    const float* Wo = (const float*)d_in[17];
    const float* bo = (const float*)d_in[18];
    float* out = (float*)d_out;

    float *hbot, *comb;
    cudaGetSymbolAddress((void**)&hbot, g_hbot);
    cudaGetSymbolAddress((void**)&comb, g_comb);

    // 1) h_bot = x @ Wi + bi          [8192,1024], K=4096
    sgemm_kernel<false><<<dim3(DBOT / 128, MTOK / 128), 256>>>(
        x, Wi, bi, nullptr, hbot, MTOK, DBOT, HDIM);

    // 2) base/fiber fused             [8192,512] x2, K=1024
    gemm23_kernel<<<dim3(8, MTOK / 128), 256>>>(hbot, Wb, bb, Wf, bf);

    //    w_logits = h_bot @ Ww + bw   [8192,8]
    wlog_kernel<<<MTOK / 8, 256>>>(Ww, bw);

    // 3) softmax / transport / aggregate -> combined [8192,128]
    pointwise_kernel<<<MTOK, 128>>>();

    // 4) out = x + combined @ Wo + bo  [8192,4096], K=128
    sgemm_kernel<true><<<dim3(HDIM / 128, MTOK / 128), 256>>>(
        comb, Wo, bo, x, out, MTOK, HDIM, COMBDIM);
}

// round 4
// speedup vs baseline: 4.9404x; 4.5431x over previous
#include <cuda_runtime.h>
#include <cuda_bf16.h>
#include <cstdint>

// Problem constants (fixed by the reference setup)
#define MTOK 8192      // B*T
#define TLEN 2048
#define HDIM 4096
#define DBOT 1024
#define PP   8
#define DD   64
#define COMBDIM 128

// ---------------- scratch (device globals) ---------------------------------
__device__ float          g_hbot   [(size_t)MTOK * DBOT];      // fp32 h_bot (for wlog)
__device__ __nv_bfloat16  g_hbot_bf[(size_t)MTOK * DBOT];      // bf16 h_bot (GEMM23 A)
__device__ float          g_bf     [(size_t)MTOK * DBOT];      // base|fiber [8192,1024]
__device__ float          g_wlog   [(size_t)MTOK * PP];
__device__ __nv_bfloat16  g_comb_bf[(size_t)MTOK * COMBDIM];
__device__ __nv_bfloat16  g_xbf    [(size_t)MTOK * HDIM];
__device__ __nv_bfloat16  g_wiT    [(size_t)DBOT * HDIM];      // Wi^T  [1024,4096]
__device__ __nv_bfloat16  g_w23T   [(size_t)DBOT * DBOT];      // [Wb|Wf]^T [1024,1024]
__device__ __nv_bfloat16  g_woT    [(size_t)HDIM * COMBDIM];   // Wo^T  [4096,128]
__device__ float          g_bias23 [DBOT];

// ---------------- PTX helpers (all plain sm_80/90 features) ----------------
__device__ __forceinline__ uint32_t smem_u32(const void* p) {
    uint32_t a;
    asm("{ .reg .u64 t; cvta.to.shared.u64 t, %1; cvt.u32.u64 %0, t; }" : "=r"(a) : "l"(p));
    return a;
}
__device__ __forceinline__ void cp16(uint32_t s, const void* g) {
    asm volatile("cp.async.cg.shared.global [%0], [%1], 16;" :: "r"(s), "l"(g));
}
__device__ __forceinline__ void cp_commit() { asm volatile("cp.async.commit_group;"); }
__device__ __forceinline__ void cp_wait0()  { asm volatile("cp.async.wait_group 0;"); }
__device__ __forceinline__ void cp_wait1()  { asm volatile("cp.async.wait_group 1;"); }

__device__ __forceinline__ void ldm_x4(uint32_t& r0, uint32_t& r1, uint32_t& r2, uint32_t& r3,
                                       uint32_t addr) {
    asm volatile("ldmatrix.sync.aligned.m8n8.x4.shared.b16 {%0,%1,%2,%3}, [%4];"
                 : "=r"(r0), "=r"(r1), "=r"(r2), "=r"(r3) : "r"(addr));
}
__device__ __forceinline__ void mma_bf16(float* d, const uint32_t* a, const uint32_t* b) {
    asm volatile("mma.sync.aligned.m16n8k16.row.col.f32.bf16.bf16.f32 "
                 "{%0,%1,%2,%3}, {%4,%5,%6,%7}, {%8,%9}, {%0,%1,%2,%3};"
                 : "+f"(d[0]), "+f"(d[1]), "+f"(d[2]), "+f"(d[3])
                 : "r"(a[0]), "r"(a[1]), "r"(a[2]), "r"(a[3]), "r"(b[0]), "r"(b[1]));
}
__device__ __forceinline__ uint32_t swz(uint32_t o) { return o ^ ((o >> 3) & 0x70u); }

// ---------------------------------------------------------------------------
// bf16 tensor-core GEMM via mma.sync (HMMA):
//   C[M,N] = A[M,K](bf16 K-major) @ Bw[N,K](bf16 K-major)^T
// Tile 128x128, BK=64, 256 threads (8 warps 4x2), 2-stage cp.async pipeline.
// MODE 0: C -> Cf(fp32) and Cbf(bf16), +bias
// MODE 1: C -> Cf, +bias
// MODE 2: C -> Cf, +bias +res
// ---------------------------------------------------------------------------
template<int MODE>
__global__ __launch_bounds__(256)
void mma_gemm(const __nv_bfloat16* __restrict__ A,
              const __nv_bfloat16* __restrict__ Bw,
              const float* __restrict__ bias,
              const float* __restrict__ res,
              float* __restrict__ Cf,
              __nv_bfloat16* __restrict__ Cbf,
              int N, int K)
{
    extern __shared__ char dsm[];
    const uint32_t tile0 = (smem_u32(dsm) + 1023u) & ~1023u;  // stage s: +s*32KB; B at +16KB

    const int tid  = threadIdx.x;
    const int lane = tid & 31;
    const int wid  = tid >> 5;
    const int wm   = wid & 3;          // 4 warps along M
    const int wn   = wid >> 2;         // 2 warps along N
    const int n0 = blockIdx.x * 128;
    const int m0 = blockIdx.y * 128;

    // ---- per-thread cp.async mapping: row r = tid>>1, 4x16B chunks --------
    const int ldr = tid >> 1;               // 0..127
    const int ldc = (tid & 1) * 4;          // chunk base 0 or 4 (16B units)

    // ---- ldmatrix lane address components ----------------------------------
    const int grp = lane >> 3;
    const int l7  = lane & 7;
    const uint32_t a_row = (uint32_t)((grp & 1) * 8 + l7);   // within m16 tile
    const uint32_t a_kb  = (uint32_t)((grp >> 1) * 16);      // 0 / 16 bytes
    const uint32_t b_row = (uint32_t)((grp >> 1) * 8 + l7);  // within n16 tile
    const uint32_t b_kb  = (uint32_t)((grp & 1) * 16);

    float acc[2][8][4];
#pragma unroll
    for (int i = 0; i < 2; i++)
#pragma unroll
        for (int j = 0; j < 8; j++)
#pragma unroll
            for (int v = 0; v < 4; v++) acc[i][j][v] = 0.0f;

    const int steps = K >> 6;

    auto load_stage = [&](int c) {
        const uint32_t sb = tile0 + (uint32_t)(c & 1) * 32768u;
        const __nv_bfloat16* ag = A  + (size_t)(m0 + ldr) * K + c * 64;
        const __nv_bfloat16* bg = Bw + (size_t)(n0 + ldr) * K + c * 64;
#pragma unroll
        for (int g = 0; g < 4; g++) {
            const uint32_t co = (uint32_t)(ldc + g) * 16u;   // byte offset in row
            cp16(sb + swz((uint32_t)ldr * 128u + co),            ag + (ldc + g) * 8);
            cp16(sb + 16384u + swz((uint32_t)ldr * 128u + co),   bg + (ldc + g) * 8);
        }
        cp_commit();
    };

    // prologue
    load_stage(0);
    if (steps > 1) load_stage(1);

    for (int s = 0; s < steps; s++) {
        if (s + 2 <= steps) cp_wait1(); else cp_wait0();
        __syncthreads();

        const uint32_t sA = tile0 + (uint32_t)(s & 1) * 32768u;
        const uint32_t sB = sA + 16384u;

#pragma unroll
        for (int ks = 0; ks < 4; ks++) {
            const uint32_t kbase = (uint32_t)ks * 32u;
            uint32_t af[2][4];
#pragma unroll
            for (int mt = 0; mt < 2; mt++) {
                const uint32_t r = (uint32_t)(wm * 32 + mt * 16) + a_row;
                ldm_x4(af[mt][0], af[mt][1], af[mt][2], af[mt][3],
                       sA + swz(r * 128u + kbase + a_kb));
            }
            uint32_t bf_[8][2];
#pragma unroll
            for (int nt2 = 0; nt2 < 4; nt2++) {
                const uint32_t r = (uint32_t)(wn * 64 + nt2 * 16) + b_row;
                uint32_t r0, r1, r2, r3;
                ldm_x4(r0, r1, r2, r3, sB + swz(r * 128u + kbase + b_kb));
                bf_[nt2 * 2 + 0][0] = r0; bf_[nt2 * 2 + 0][1] = r1;
                bf_[nt2 * 2 + 1][0] = r2; bf_[nt2 * 2 + 1][1] = r3;
            }
#pragma unroll
            for (int mt = 0; mt < 2; mt++)
#pragma unroll
                for (int nt = 0; nt < 8; nt++)
                    mma_bf16(acc[mt][nt], af[mt], bf_[nt]);
        }

        __syncthreads();            // done reading buffer (s&1)
        if (s + 2 < steps) load_stage(s + 2);
    }

    // ---- epilogue -----------------------------------------------------------
#pragma unroll
    for (int mt = 0; mt < 2; mt++) {
        const int rbase = m0 + wm * 32 + mt * 16 + (lane >> 2);
#pragma unroll
        for (int nt = 0; nt < 8; nt++) {
            const int col = n0 + wn * 64 + nt * 8 + 2 * (lane & 3);
            const float2 bv = *reinterpret_cast<const float2*>(bias + col);
#pragma unroll
            for (int h = 0; h < 2; h++) {
                const int row = rbase + h * 8;
                float2 v;
                v.x = acc[mt][nt][h * 2 + 0] + bv.x;
                v.y = acc[mt][nt][h * 2 + 1] + bv.y;
                if (MODE == 2) {
                    float2 rv = *reinterpret_cast<const float2*>(res + (size_t)row * N + col);
                    v.x += rv.x; v.y += rv.y;
                }
                *reinterpret_cast<float2*>(Cf + (size_t)row * N + col) = v;
                if (MODE == 0) {
                    *reinterpret_cast<__nv_bfloat162*>(Cbf + (size_t)row * N + col) =
                        __nv_bfloat162(__float2bfloat16(v.x), __float2bfloat16(v.y));
                }
            }
        }
    }
}

// ---------------------------------------------------------------------------
// conversion kernels
// ---------------------------------------------------------------------------
__global__ __launch_bounds__(256)
void castx_kernel(const float* __restrict__ in, __nv_bfloat16* __restrict__ out)
{
    const size_t i = (size_t)blockIdx.x * 256 + threadIdx.x;   // float4 index
    float4 v = reinterpret_cast<const float4*>(in)[i];
    __nv_bfloat162* o = reinterpret_cast<__nv_bfloat162*>(out) + i * 2;
    o[0] = __nv_bfloat162(__float2bfloat16(v.x), __float2bfloat16(v.y));
    o[1] = __nv_bfloat162(__float2bfloat16(v.z), __float2bfloat16(v.w));
}

// in [K,N] f32 row-major  ->  out [N,K] bf16 row-major  (32x32 tiles)
__global__ __launch_bounds__(256)
void tcast_kernel(const float* __restrict__ in, __nv_bfloat16* __restrict__ out,
                  int K, int N)
{
    __shared__ float t[32][33];
    const int n0 = blockIdx.x * 32, k0 = blockIdx.y * 32;
    const int tx = threadIdx.x & 31, ty = threadIdx.x >> 5;   // 32 x 8
#pragma unroll
    for (int i = 0; i < 32; i += 8)
        t[ty + i][tx] = in[(size_t)(k0 + ty + i) * N + n0 + tx];
    __syncthreads();
#pragma unroll
    for (int i = 0; i < 32; i += 8)
        out[(size_t)(n0 + ty + i) * K + k0 + tx] = __float2bfloat16(t[tx][ty + i]);
}

__global__ void biascat_kernel(const float* __restrict__ bb, const float* __restrict__ bf)
{
    const int i = threadIdx.x;
    g_bias23[i]       = bb[i];
    g_bias23[i + 512] = bf[i];
}

// ---------------------------------------------------------------------------
// w_logits (fp32, reads fp32 h_bot): warp per token, coalesced Ww rows
// ---------------------------------------------------------------------------
__global__ __launch_bounds__(256)
void wlog_kernel(const float* __restrict__ Ww, const float* __restrict__ bw)
{
    const int warp = threadIdx.x >> 5;
    const int lane = threadIdx.x & 31;
    const int t = blockIdx.x * 8 + warp;
    const float* h = g_hbot + (size_t)t * DBOT;

    float acc[PP];
#pragma unroll
    for (int p = 0; p < PP; p++) acc[p] = 0.0f;
#pragma unroll 4
    for (int k = lane; k < DBOT; k += 32) {
        const float hv = h[k];
        float4 w0 = *reinterpret_cast<const float4*>(Ww + (size_t)k * PP);
        float4 w1 = *reinterpret_cast<const float4*>(Ww + (size_t)k * PP + 4);
        acc[0] = fmaf(hv, w0.x, acc[0]); acc[1] = fmaf(hv, w0.y, acc[1]);
        acc[2] = fmaf(hv, w0.z, acc[2]); acc[3] = fmaf(hv, w0.w, acc[3]);
        acc[4] = fmaf(hv, w1.x, acc[4]); acc[5] = fmaf(hv, w1.y, acc[5]);
        acc[6] = fmaf(hv, w1.z, acc[6]); acc[7] = fmaf(hv, w1.w, acc[7]);
    }
#pragma unroll
    for (int p = 0; p < PP; p++)
#pragma unroll
        for (int o = 16; o > 0; o >>= 1)
            acc[p] += __shfl_xor_sync(0xffffffffu, acc[p], o);
    if (lane < PP)
        g_wlog[(size_t)t * PP + lane] = acc[lane] + bw[lane];
}

// ---------------------------------------------------------------------------
// Pointwise: clip base, temporal transport, softmax over P, aggregate -> bf16
// ---------------------------------------------------------------------------
__global__ __launch_bounds__(128)
void pointwise_kernel()
{
    const int t   = blockIdx.x;
    const int bt  = t & (TLEN - 1);
    const int tid = threadIdx.x;

    __shared__ float w[PP];
    if (tid < PP) w[tid] = g_wlog[(size_t)t * PP + tid];
    __syncthreads();
    if (tid == 0) {
        float mx = w[0];
#pragma unroll
        for (int p = 1; p < PP; p++) mx = fmaxf(mx, w[p]);
        float sum = 0.0f;
#pragma unroll
        for (int p = 0; p < PP; p++) { w[p] = __expf(w[p] - mx); sum += w[p]; }
        const float inv = 1.0f / sum;
#pragma unroll
        for (int p = 0; p < PP; p++) w[p] *= inv;
    }
    __syncthreads();

    float out = 0.0f;
    if (tid < DD) {
        const int d = tid;
        const float* bc = g_bf + (size_t)t * DBOT;
        if (bt == 0) {
#pragma unroll
            for (int p = 0; p < PP; p++) {
                float c = fminf(fmaxf(bc[p * DD + d], -10.0f), 10.0f);
                out += w[p] * c;
            }
        } else {
            const float* bp = g_bf + (size_t)(t - 1) * DBOT;
#pragma unroll
            for (int p = 0; p < PP; p++) {
                float c  = fminf(fmaxf(bc[p * DD + d], -10.0f), 10.0f);
                float pv = fminf(fmaxf(bp[p * DD + d], -10.0f), 10.0f);
                out += w[p] * (0.9f * c + 0.1f * pv);
            }
        }
    } else {
        const int kd = tid - DD;
        const float* f = g_bf + (size_t)t * DBOT + 512;
#pragma unroll
        for (int p = 0; p < PP; p++)
            out += w[p] * f[p * DD + kd];
    }
    g_comb_bf[(size_t)t * COMBDIM + tid] = __float2bfloat16(out);
}

// ---------------------------------------------------------------------------
// Inputs: 0:x 1:Wi 2:bi 3:Wb 4:bb 5:Wf 6:bf 7:Wl 8:bl 9:Ww 10:bw
//         11:Wm 12:bm 13:Ws 14:bs 15:Wu 16:bu 17:Wo 18:bo
// ---------------------------------------------------------------------------
static const int SMEM_DYN = 2 * 32768 + 1024;

extern "C" void kernel_launch(void* const* d_in, const int* in_sizes, int n_in,
                              void* d_out, int out_size)
{
    const float* x  = (const float*)d_in[0];
    const float* Wi = (const float*)d_in[1];
    const float* bi = (const float*)d_in[2];
    const float* Wb = (const float*)d_in[3];
    const float* bb = (const float*)d_in[4];
    const float* Wf = (const float*)d_in[5];
    const float* bf = (const float*)d_in[6];
    const float* Ww = (const float*)d_in[9];
    const float* bw = (const float*)d_in[10];
    const float* Wo = (const float*)d_in[17];
    const float* bo = (const float*)d_in[18];
    float* out = (float*)d_out;

    float *hbot, *bfc, *b23;
    __nv_bfloat16 *hbotbf, *combbf, *xbf, *wiT, *w23T, *woT;
    cudaGetSymbolAddress((void**)&hbot,   g_hbot);
    cudaGetSymbolAddress((void**)&hbotbf, g_hbot_bf);
    cudaGetSymbolAddress((void**)&bfc,    g_bf);
    cudaGetSymbolAddress((void**)&combbf, g_comb_bf);
    cudaGetSymbolAddress((void**)&xbf,    g_xbf);
    cudaGetSymbolAddress((void**)&wiT,    g_wiT);
    cudaGetSymbolAddress((void**)&w23T,   g_w23T);
    cudaGetSymbolAddress((void**)&woT,    g_woT);
    cudaGetSymbolAddress((void**)&b23,    g_bias23);

    cudaFuncSetAttribute(mma_gemm<0>, cudaFuncAttributeMaxDynamicSharedMemorySize, SMEM_DYN);
    cudaFuncSetAttribute(mma_gemm<1>, cudaFuncAttributeMaxDynamicSharedMemorySize, SMEM_DYN);
    cudaFuncSetAttribute(mma_gemm<2>, cudaFuncAttributeMaxDynamicSharedMemorySize, SMEM_DYN);

    // ---- conversions -------------------------------------------------------
    castx_kernel<<<(MTOK * HDIM / 4) / 256, 256>>>(x, xbf);
    tcast_kernel<<<dim3(DBOT / 32, HDIM / 32), 256>>>(Wi, wiT, HDIM, DBOT);
    tcast_kernel<<<dim3(512 / 32, DBOT / 32), 256>>>(Wb, w23T, DBOT, 512);
    tcast_kernel<<<dim3(512 / 32, DBOT / 32), 256>>>(Wf, w23T + (size_t)512 * DBOT, DBOT, 512);
    tcast_kernel<<<dim3(HDIM / 32, COMBDIM / 32), 256>>>(Wo, woT, COMBDIM, HDIM);
    biascat_kernel<<<1, 512>>>(bb, bf);

    // ---- GEMM1: h_bot = x @ Wi + bi  [8192,1024], K=4096 -------------------
    mma_gemm<0><<<dim3(DBOT / 128, MTOK / 128), 256, SMEM_DYN>>>(
        xbf, wiT, bi, nullptr, hbot, hbotbf, DBOT, HDIM);

    // ---- GEMM23: base|fiber = h_bot @ [Wb|Wf] + bias  [8192,1024], K=1024 --
    mma_gemm<1><<<dim3(DBOT / 128, MTOK / 128), 256, SMEM_DYN>>>(
        hbotbf, w23T, b23, nullptr, bfc, nullptr, DBOT, DBOT);

    // ---- w_logits (fp32) ---------------------------------------------------
    wlog_kernel<<<MTOK / 8, 256>>>(Ww, bw);

    // ---- pointwise ---------------------------------------------------------
    pointwise_kernel<<<MTOK, 128>>>();

    // ---- GEMM4: out = x + combined @ Wo + bo  [8192,4096], K=128 -----------
    mma_gemm<2><<<dim3(HDIM / 128, MTOK / 128), 256, SMEM_DYN>>>(
        combbf, woT, bo, x, out, nullptr, HDIM, COMBDIM);
}